// round 16
// baseline (speedup 1.0000x reference)
#include <cuda_runtime.h>
#include <cuda_fp16.h>
#include <cstdint>

// Problem constants
#define BATCH 4
#define SEQ   8192
#define DIM   4096
#define NEXP  64
#define CAP   256
#define ROWS  (BATCH * SEQ)      // 32768

// GEMM tiling (R15 config): 128 rows/CTA, 256 thr, KT=32, 2 CTA/SM
#define TILE_R 128
#define NTHR   256
#define KT     32
#define NCHUNK (DIM / KT)        // 128

// W pre-scaled by 2^10 in prep; logits unscaled by 2^-10 (exact).
#define WSCALE   1024.0f
#define WUNSCALE 0.0009765625f

// smem: fp16 tiles, row stride 40 halves (80 bytes) -> conflict-free ldmatrix
#define AS_BYTE 80
#define AHI_OFF 0
#define ALO_OFF 10240
#define BHI_OFF 20480
#define BLO_OFF 25600
#define BUF_STRIDE 30720
#define SMEM_BYTES (2 * BUF_STRIDE)   // 61440

// epilogue smem reuse
#define PS_STRIDE 130
#define RED_OFF   34048           // Ps = 64*130*4 = 33280

// scratch
__device__ __half g_Whi[NEXP * DIM];                     // W hi (scaled fp16)
__device__ __half g_Wlo[NEXP * DIM];                     // W lo (scaled fp16)
__device__ float  g_probsT[(size_t)BATCH * NEXP * SEQ];  // [B][E][S]

// ---------------------------------------------------------------------------
__device__ __forceinline__ uint32_t smem_u32(const void* p) {
    uint32_t a;
    asm("{ .reg .u64 t; cvta.to.shared.u64 t, %1; cvt.u32.u64 %0, t; }" : "=r"(a) : "l"(p));
    return a;
}
__device__ __forceinline__ void cp_async16(void* smem_dst, const void* gmem_src) {
    unsigned s = (unsigned)__cvta_generic_to_shared(smem_dst);
    asm volatile("cp.async.cg.shared.global [%0], [%1], 16;\n" :: "r"(s), "l"(gmem_src) : "memory");
}
__device__ __forceinline__ void cp_commit() {
    asm volatile("cp.async.commit_group;\n" ::: "memory");
}
__device__ __forceinline__ void cp_wait0() {
    asm volatile("cp.async.wait_group 0;\n" ::: "memory");
}

__device__ __forceinline__ void ldsm_x4(uint32_t& r0, uint32_t& r1, uint32_t& r2,
                                        uint32_t& r3, uint32_t addr) {
    asm volatile("ldmatrix.sync.aligned.m8n8.x4.shared.b16 {%0,%1,%2,%3}, [%4];"
                 : "=r"(r0), "=r"(r1), "=r"(r2), "=r"(r3) : "r"(addr));
}

__device__ __forceinline__ void mma_fp16(float* d, const uint32_t* a,
                                         uint32_t b0, uint32_t b1) {
    asm volatile("mma.sync.aligned.m16n8k16.row.col.f32.f16.f16.f32 "
                 "{%0,%1,%2,%3}, {%4,%5,%6,%7}, {%8,%9}, {%0,%1,%2,%3};"
                 : "+f"(d[0]), "+f"(d[1]), "+f"(d[2]), "+f"(d[3])
                 : "r"(a[0]), "r"(a[1]), "r"(a[2]), "r"(a[3]), "r"(b0), "r"(b1));
}

// ---------------------------------------------------------------------------
// Kernel 0: prep = W fp32 -> scaled fp16 hi/lo split only (mask zeroing moved
// into the GEMM epilogue).
// ---------------------------------------------------------------------------
__global__ void __launch_bounds__(256)
prep_kernel(const float* __restrict__ W)
{
    int i = blockIdx.x * 256 + threadIdx.x;     // one float2 per thread
    float2 w = *(const float2*)(W + 2 * i);
    w.x *= WSCALE; w.y *= WSCALE;
    __half2 h = __floats2half2_rn(w.x, w.y);
    float rx = w.x - __half2float(__low2half(h));
    float ry = w.y - __half2float(__high2half(h));
    __half2 l = __floats2half2_rn(rx, ry);
    *(__half2*)(g_Whi + 2 * i) = h;
    *(__half2*)(g_Wlo + 2 * i) = l;
}

// ---------------------------------------------------------------------------
// Kernel 1: HMMA fp16-split router GEMM + fused softmax.
// W tiles via cp.async from pre-converted g_Whi/g_Wlo; X: LDG->split->STS.
// NEW: each CTA zeros its own 128-row mask slice (drains behind the epilogue).
// 4x2 warp grid. Grid 256 x 256 threads, 2 CTAs/SM.
// ---------------------------------------------------------------------------
__global__ void __launch_bounds__(NTHR, 2)
router_gemm_kernel(const float* __restrict__ X, float* __restrict__ mask,
                   float* __restrict__ probs_out, float* __restrict__ logits_out)
{
    extern __shared__ char smem[];
    const uint32_t sbase = smem_u32(smem);
    const int tid  = threadIdx.x;
    const int wid  = tid >> 5;
    const int lane = tid & 31;
    const int wr   = wid & 3;     // row group (32 rows)
    const int wc   = wid >> 2;    // expert group (32 experts)
    const int row0 = blockIdx.x * TILE_R;

    float d[2][4][4];
#pragma unroll
    for (int mf = 0; mf < 2; mf++)
#pragma unroll
        for (int g = 0; g < 4; g++)
#pragma unroll
            for (int j = 0; j < 4; j++) d[mf][g][j] = 0.f;

    uint32_t a_off[2], b_off[2];
#pragma unroll
    for (int mf = 0; mf < 2; mf++)
        a_off[mf] = (uint32_t)((wr * 32 + mf * 16 + ((lane >> 3) & 1) * 8 + (lane & 7)) * AS_BYTE
                               + ((lane >> 4) & 1) * 16);
#pragma unroll
    for (int bg = 0; bg < 2; bg++)
        b_off[bg] = (uint32_t)((wc * 32 + bg * 16 + ((lane >> 4) & 1) * 8 + (lane & 7)) * AS_BYTE
                               + ((lane >> 3) & 1) * 16);

    float4 xr[4];   // X register staging

    auto load_chunk = [&](int t) {
        const int k0 = t * KT;
#pragma unroll
        for (int m = 0; m < 4; m++) {
            int f = tid + m * 256;           // float4 slot, 8 per row
            int r = f >> 3, c4 = f & 7;
            xr[m] = *(const float4*)(X + (size_t)(row0 + r) * DIM + k0 + c4 * 4);
        }
    };

    auto fill_W = [&](int t, int buf) {
        char* bp = smem + buf * BUF_STRIDE;
        const int k0 = t * KT;
#pragma unroll
        for (int m = 0; m < 2; m++) {
            int i = tid + m * 256;          // 0..511
            int term = i >> 8;              // 0 = hi, 1 = lo
            int j    = i & 255;
            int e    = j >> 2;              // expert row 0..63
            int c16  = j & 3;               // 16B chunk within 64B row data
            char* dst = bp + (term ? BLO_OFF : BHI_OFF) + e * AS_BYTE + c16 * 16;
            const __half* src = (term ? g_Wlo : g_Whi) + (size_t)e * DIM + k0 + c16 * 8;
            cp_async16(dst, src);
        }
    };

    auto cvt_store = [&](float4 v, char* hi_b, char* lo_b, uint32_t byte_off) {
        __half2 h0 = __floats2half2_rn(v.x, v.y);
        __half2 h1 = __floats2half2_rn(v.z, v.w);
        float rx = v.x - __half2float(__low2half(h0));
        float ry = v.y - __half2float(__high2half(h0));
        float rz = v.z - __half2float(__low2half(h1));
        float rw = v.w - __half2float(__high2half(h1));
        __half2 l0 = __floats2half2_rn(rx, ry);
        __half2 l1 = __floats2half2_rn(rz, rw);
        *(uint2*)(hi_b + byte_off) = make_uint2(*(uint32_t*)&h0, *(uint32_t*)&h1);
        *(uint2*)(lo_b + byte_off) = make_uint2(*(uint32_t*)&l0, *(uint32_t*)&l1);
    };

    auto store_chunk = [&](int buf) {
        char* bp = smem + buf * BUF_STRIDE;
#pragma unroll
        for (int m = 0; m < 4; m++) {
            int f = tid + m * 256;
            int r = f >> 3, c4 = f & 7;
            cvt_store(xr[m], bp + AHI_OFF, bp + ALO_OFF, (uint32_t)(r * AS_BYTE + c4 * 8));
        }
    };

    auto compute_chunk = [&](int buf) {
        const uint32_t bb = sbase + buf * BUF_STRIDE;
#pragma unroll
        for (int ks = 0; ks < 2; ks++) {
            const uint32_t kb = ks * 32;
            uint32_t ah[2][4], al[2][4];
#pragma unroll
            for (int mf = 0; mf < 2; mf++) {
                ldsm_x4(ah[mf][0], ah[mf][1], ah[mf][2], ah[mf][3], bb + AHI_OFF + a_off[mf] + kb);
                ldsm_x4(al[mf][0], al[mf][1], al[mf][2], al[mf][3], bb + ALO_OFF + a_off[mf] + kb);
            }
#pragma unroll
            for (int bg = 0; bg < 2; bg++) {
                uint32_t bh[4], bl[4];
                ldsm_x4(bh[0], bh[1], bh[2], bh[3], bb + BHI_OFF + b_off[bg] + kb);
                ldsm_x4(bl[0], bl[1], bl[2], bl[3], bb + BLO_OFF + b_off[bg] + kb);
#pragma unroll
                for (int mf = 0; mf < 2; mf++) {
                    mma_fp16(d[mf][2 * bg],     ah[mf], bh[0], bh[1]);
                    mma_fp16(d[mf][2 * bg],     ah[mf], bl[0], bl[1]);
                    mma_fp16(d[mf][2 * bg],     al[mf], bh[0], bh[1]);
                    mma_fp16(d[mf][2 * bg + 1], ah[mf], bh[2], bh[3]);
                    mma_fp16(d[mf][2 * bg + 1], ah[mf], bl[2], bl[3]);
                    mma_fp16(d[mf][2 * bg + 1], al[mf], bh[2], bh[3]);
                }
            }
        }
    };

    fill_W(0, 0); cp_commit();
    load_chunk(0);
    store_chunk(0);
    cp_wait0();
    __syncthreads();

    for (int t = 0; t < NCHUNK; t++) {
        const bool more = (t + 1 < NCHUNK);
        if (more) { fill_W(t + 1, (t + 1) & 1); cp_commit(); load_chunk(t + 1); }
        compute_chunk(t & 1);
        if (more) { store_chunk((t + 1) & 1); cp_wait0(); }
        __syncthreads();
    }

    // zero this CTA's mask slice (issues early; drains behind epilogue math)
    {
        float4* m4 = (float4*)(mask + (size_t)row0 * NEXP);
#pragma unroll
        for (int m = 0; m < 8; m++)     // 2048 float4 / 256 thr
            m4[tid + m * NTHR] = make_float4(0.f, 0.f, 0.f, 0.f);
    }

    // Epilogue: softmax across the 2 expert-group warps via smem exchange.
    float* Ps     = (float*)smem;                 // [64][130]
    float* sm_max = (float*)(smem + RED_OFF);     // [128][2]
    float* sm_sum = sm_max + 256;                 // [128][2]
    const int q  = lane >> 2;
    const int c2 = (lane & 3) * 2;
    float pmax[2][2];

#pragma unroll
    for (int mf = 0; mf < 2; mf++)
#pragma unroll
    for (int half = 0; half < 2; half++) {
        const int r = wr * 32 + mf * 16 + q + half * 8;
        float v[8];
#pragma unroll
        for (int g = 0; g < 4; g++) {
            v[2 * g]     = d[mf][g][2 * half]     * WUNSCALE;
            v[2 * g + 1] = d[mf][g][2 * half + 1] * WUNSCALE;
        }
        float mx = v[0];
#pragma unroll
        for (int c = 1; c < 8; c++) mx = fmaxf(mx, v[c]);
        mx = fmaxf(mx, __shfl_xor_sync(0xFFFFFFFFu, mx, 1));
        mx = fmaxf(mx, __shfl_xor_sync(0xFFFFFFFFu, mx, 2));
        float ssum = 0.f;
#pragma unroll
        for (int c = 0; c < 8; c++) {
            float e = expf(v[c] - mx);
            d[mf][c >> 1][2 * half + (c & 1)] = e;   // cache exp
            ssum += e;
        }
        ssum += __shfl_xor_sync(0xFFFFFFFFu, ssum, 1);
        ssum += __shfl_xor_sync(0xFFFFFFFFu, ssum, 2);
        pmax[mf][half] = mx;

        const size_t grow = (size_t)(row0 + r) * NEXP + wc * 32;
#pragma unroll
        for (int g = 0; g < 4; g++)
            *(float2*)(logits_out + grow + g * 8 + c2) = make_float2(v[2 * g], v[2 * g + 1]);

        if ((lane & 3) == 0) {
            sm_max[r * 2 + wc] = mx;
            sm_sum[r * 2 + wc] = ssum;
        }
    }
    __syncthreads();

#pragma unroll
    for (int mf = 0; mf < 2; mf++)
#pragma unroll
    for (int half = 0; half < 2; half++) {
        const int r = wr * 32 + mf * 16 + q + half * 8;
        float m0 = sm_max[r * 2], m1 = sm_max[r * 2 + 1];
        float s0 = sm_sum[r * 2], s1 = sm_sum[r * 2 + 1];
        float M = fmaxf(m0, m1);
        float S = s0 * expf(m0 - M) + s1 * expf(m1 - M);
        float scale = expf(pmax[mf][half] - M) / S;

        const size_t grow = (size_t)(row0 + r) * NEXP + wc * 32;
#pragma unroll
        for (int g = 0; g < 4; g++) {
            const int col = wc * 32 + g * 8 + c2;
            float p0 = d[mf][g][2 * half]     * scale;
            float p1 = d[mf][g][2 * half + 1] * scale;
            *(float2*)(probs_out + grow + g * 8 + c2) = make_float2(p0, p1);
            Ps[col * PS_STRIDE + r]       = p0;
            Ps[(col + 1) * PS_STRIDE + r] = p1;
        }
    }
    __syncthreads();

    const int bb2 = row0 >> 13;
    const int s0i = row0 & (SEQ - 1);
#pragma unroll
    for (int m = 0; m < 32; m++) {
        int idx = tid + m * NTHR;       // 0..8191
        int e = idx >> 7, r = idx & 127;
        g_probsT[((size_t)(bb2 * NEXP + e)) * SEQ + s0i + r] = Ps[e * PS_STRIDE + r];
    }
}

// ---------------------------------------------------------------------------
// Kernel 2: per-(b,e) exact top-CAP radix select + mask scatter.
// Values in 16 registers/thread; after the threshold is found, selected
// tokens scatter mask[b,s,0] = 1 directly (mask zeroed by the GEMM;
// duplicate writers across experts store the identical value).
// ---------------------------------------------------------------------------
__global__ void __launch_bounds__(512)
thr_kernel(float* __restrict__ mask)
{
    __shared__ unsigned hist[256];
    __shared__ unsigned sel_prefix, sel_remaining;

    const int be   = blockIdx.x;
    const int tid  = threadIdx.x;
    const int lane = tid & 31;
    const unsigned* col = (const unsigned*)(g_probsT + (size_t)be * SEQ);

    unsigned v[16];
#pragma unroll
    for (int m = 0; m < 16; m++) v[m] = col[tid + m * 512];
    if (tid == 0) { sel_prefix = 0u; sel_remaining = CAP; }
    __syncthreads();

    for (int pass = 0; pass < 4; pass++) {
        const int shift = 24 - 8 * pass;
        const unsigned himask = pass ? (0xFFFFFFFFu << (shift + 8)) : 0u;
        if (tid < 256) hist[tid] = 0u;
        __syncthreads();
        const unsigned pfx = sel_prefix;
#pragma unroll
        for (int m = 0; m < 16; m++) {
            if ((v[m] & himask) == pfx)
                atomicAdd(&hist[(v[m] >> shift) & 255u], 1u);
        }
        __syncthreads();

        if (tid < 32) {
            unsigned b[8], s[8];
#pragma unroll
            for (int k = 0; k < 8; k++) b[k] = hist[lane * 8 + k];
            s[7] = b[7];
#pragma unroll
            for (int k = 6; k >= 0; k--) s[k] = b[k] + s[k + 1];
            unsigned T = s[0];
            unsigned incl = T;
#pragma unroll
            for (int off = 1; off < 32; off <<= 1) {
                unsigned u = __shfl_down_sync(0xFFFFFFFFu, incl, off);
                if (lane + off < 32) incl += u;
            }
            const unsigned excl = incl - T;
            const unsigned rem = sel_remaining;
#pragma unroll
            for (int k = 0; k < 8; k++) {
                unsigned suf = excl + s[k];
                unsigned nxt = suf - b[k];
                if (suf >= rem && nxt < rem) {
                    sel_prefix = pfx | ((unsigned)(lane * 8 + k) << shift);
                    sel_remaining = rem - nxt;
                }
            }
        }
        __syncthreads();
    }

    const unsigned thr = sel_prefix;
    const int bb = be >> 6;
    float* mrow = mask + (size_t)bb * SEQ * NEXP;
#pragma unroll
    for (int m = 0; m < 16; m++) {
        if (v[m] >= thr) {
            int s = tid + m * 512;
            mrow[(size_t)s * NEXP] = 1.0f;
        }
    }
}

// ---------------------------------------------------------------------------
extern "C" void kernel_launch(void* const* d_in, const int* in_sizes, int n_in,
                              void* d_out, int out_size)
{
    const float* X = (const float*)d_in[0];   // [4, 8192, 4096]
    const float* W = (const float*)d_in[1];   // [64, 4096]

    float* mask   = (float*)d_out;
    float* probs  = mask  + (size_t)BATCH * SEQ * NEXP;
    float* logits = probs + (size_t)BATCH * SEQ * NEXP;

    // prep: W -> scaled fp16 hi/lo (131072 float2 / 256 thr = 512 blocks)
    prep_kernel<<<(NEXP * DIM / 2) / 256, 256>>>(W);

    cudaFuncSetAttribute(router_gemm_kernel,
                         cudaFuncAttributeMaxDynamicSharedMemorySize, SMEM_BYTES);
    router_gemm_kernel<<<ROWS / TILE_R, NTHR, SMEM_BYTES>>>(X, mask, probs, logits);

    thr_kernel<<<BATCH * NEXP, 512>>>(mask);
}